// round 1
// baseline (speedup 1.0000x reference)
#include <cuda_runtime.h>
#include <math.h>

#define VOCAB 32000
#define D_IN  512
#define D_H   1024
#define D3H   3072
#define D_OUT 64
#define BB    64
#define SS    256

typedef unsigned long long u64t;

// ---------------- scratch (static device globals; zero-init at load) ----------
__device__ float g_gi[(size_t)SS * BB * D3H];   // input projections [s][b][3H]
__device__ float g_hs[(size_t)SS * BB * D_H];   // hidden states    [s][b][H]
__device__ float g_h0[BB * D_H];                // all-zero h(-1), never written

// ---------------- f32x2 helpers ------------------------------------------------
__device__ __forceinline__ void fma2(u64t& c, u64t a, u64t b) {
    asm("fma.rn.f32x2 %0, %1, %2, %0;" : "+l"(c) : "l"(a), "l"(b));
}
__device__ __forceinline__ float2 up2(u64t v) {
    float2 r;
    asm("mov.b64 {%0, %1}, %2;" : "=f"(r.x), "=f"(r.y) : "l"(v));
    return r;
}

// ==============================================================================
// Kernel 1: gi = emb[x] @ w_ih^T + b_ih      (M=16384, N=3072, K=512)
// 128x128x16 tile, 256 threads, 8x8 per thread, f32x2 inner loop.
// A operand duplicated in SMEM (broadcast side), B paired naturally.
// ==============================================================================
__global__ __launch_bounds__(256) void gi_gemm(
    const int* __restrict__ x, const float* __restrict__ emb,
    const float* __restrict__ w_ih, const float* __restrict__ b_ih)
{
    __shared__ float2 As2[16][128];   // 16 KB (duplicated)
    __shared__ float  Bs [16][128];   //  8 KB

    const int tid   = threadIdx.x;
    const int m_blk = blockIdx.y * 128;
    const int n_blk = blockIdx.x * 128;

    // gather setup: 2 A-load slots and 2 B-load slots per thread
    const float* aptr[2]; int arow[2], akq[2];
    const float* bptr[2]; int brow[2], bkq[2];
#pragma unroll
    for (int t = 0; t < 2; t++) {
        int i   = tid + t * 256;            // 0..511
        arow[t] = i >> 2;                   // 0..127
        akq[t]  = (i & 3) * 4;
        int m = m_blk + arow[t];
        int s = m >> 6, b = m & 63;         // m = s*B + b
        int tok = x[b * SS + s];
        aptr[t] = emb + (size_t)tok * D_IN;
        brow[t] = arow[t]; bkq[t] = akq[t];
        bptr[t] = w_ih + (size_t)(n_blk + brow[t]) * D_IN;
    }

    u64t c2[8][4];
#pragma unroll
    for (int i = 0; i < 8; i++)
#pragma unroll
        for (int j = 0; j < 4; j++) c2[i][j] = 0ull;

    const int ty = tid >> 4, tx = tid & 15;

    for (int kt = 0; kt < D_IN; kt += 16) {
#pragma unroll
        for (int t = 0; t < 2; t++) {
            float4 v = *(const float4*)(aptr[t] + kt + akq[t]);
            As2[akq[t]+0][arow[t]] = make_float2(v.x, v.x);
            As2[akq[t]+1][arow[t]] = make_float2(v.y, v.y);
            As2[akq[t]+2][arow[t]] = make_float2(v.z, v.z);
            As2[akq[t]+3][arow[t]] = make_float2(v.w, v.w);
            float4 w = *(const float4*)(bptr[t] + kt + bkq[t]);
            Bs[bkq[t]+0][brow[t]] = w.x;
            Bs[bkq[t]+1][brow[t]] = w.y;
            Bs[bkq[t]+2][brow[t]] = w.z;
            Bs[bkq[t]+3][brow[t]] = w.w;
        }
        __syncthreads();
#pragma unroll
        for (int k = 0; k < 16; k++) {
            u64t ad[8], bb[4];
#pragma unroll
            for (int i = 0; i < 4; i++) {
                ad[i]     = *(const u64t*)&As2[k][ty*4 + i];
                ad[i + 4] = *(const u64t*)&As2[k][64 + ty*4 + i];
            }
            bb[0] = *(const u64t*)&Bs[k][tx*4];
            bb[1] = *(const u64t*)&Bs[k][tx*4 + 2];
            bb[2] = *(const u64t*)&Bs[k][64 + tx*4];
            bb[3] = *(const u64t*)&Bs[k][64 + tx*4 + 2];
#pragma unroll
            for (int i = 0; i < 8; i++)
#pragma unroll
                for (int j = 0; j < 4; j++)
                    fma2(c2[i][j], ad[i], bb[j]);
        }
        __syncthreads();
    }

#pragma unroll
    for (int i = 0; i < 8; i++) {
        int mi = (i < 4) ? (ty*4 + i) : (64 + ty*4 + (i - 4));
        size_t m = (size_t)(m_blk + mi);
#pragma unroll
        for (int j = 0; j < 4; j++) {
            int nj = (j < 2) ? (tx*4 + j*2) : (64 + tx*4 + (j - 2)*2);
            int n  = n_blk + nj;
            float2 v = up2(c2[i][j]);
            v.x += b_ih[n];
            v.y += b_ih[n + 1];
            *(float2*)(g_gi + m * D3H + n) = v;
        }
    }
}

// ==============================================================================
// Kernel 2: one GRU step.  gh = h_prev @ w_hh^T (+b_hh), fused gates.
// Grid 128 CTAs: CTA owns 8 j's (all 3 gate rows), all 64 batch rows.
// 128 threads: thread = (mg 0..15, jj 0..7) -> 4 b's x {r,z,n} of one j.
// ==============================================================================
__global__ __launch_bounds__(128) void gru_step(
    const int s, const float* __restrict__ w_hh, const float* __restrict__ b_hh)
{
    __shared__ float  Hs [32][64];    // 8 KB
    __shared__ float2 Ws2[32][24];    // 6 KB (duplicated weights)

    const float* __restrict__ h_prev = (s == 0) ? g_h0 : (g_hs + (size_t)(s - 1) * BB * D_H);
    float*       __restrict__ h_out  = g_hs + (size_t)s * BB * D_H;
    const float* __restrict__ gi_s   = g_gi + (size_t)s * BB * D3H;

    const int tid = threadIdx.x;
    const int j0  = blockIdx.x * 8;
    const int mg  = tid >> 3, jj = tid & 7;
    const int m0  = mg * 4;
    const int j   = j0 + jj;

    u64t c2[3][2] = {{0ull,0ull},{0ull,0ull},{0ull,0ull}};

    for (int kt = 0; kt < D_H; kt += 32) {
#pragma unroll
        for (int t = 0; t < 4; t++) {
            int i = tid + t * 128;          // 0..511
            int b = i >> 3, kq = (i & 7) * 4;
            float4 v = *(const float4*)(h_prev + b * D_H + kt + kq);
            Hs[kq+0][b] = v.x; Hs[kq+1][b] = v.y;
            Hs[kq+2][b] = v.z; Hs[kq+3][b] = v.w;
        }
#pragma unroll
        for (int t = 0; t < 2; t++) {
            int i = tid + t * 128;          // 0..255, need 192
            if (i < 192) {
                int r = i >> 3, kq = (i & 7) * 4;
                int gate = r >> 3, jr = r & 7;
                const float* wp = w_hh + (size_t)(gate * D_H + j0 + jr) * D_H + kt + kq;
                float4 v = *(const float4*)wp;
                Ws2[kq+0][r] = make_float2(v.x, v.x);
                Ws2[kq+1][r] = make_float2(v.y, v.y);
                Ws2[kq+2][r] = make_float2(v.z, v.z);
                Ws2[kq+3][r] = make_float2(v.w, v.w);
            }
        }
        __syncthreads();
#pragma unroll
        for (int k = 0; k < 32; k++) {
            u64t a01 = *(const u64t*)&Hs[k][m0];
            u64t a23 = *(const u64t*)&Hs[k][m0 + 2];
            u64t br  = *(const u64t*)&Ws2[k][jj];
            u64t bz  = *(const u64t*)&Ws2[k][8 + jj];
            u64t bn  = *(const u64t*)&Ws2[k][16 + jj];
            fma2(c2[0][0], a01, br); fma2(c2[0][1], a23, br);
            fma2(c2[1][0], a01, bz); fma2(c2[1][1], a23, bz);
            fma2(c2[2][0], a01, bn); fma2(c2[2][1], a23, bn);
        }
        __syncthreads();
    }

    float gh[3][4];
#pragma unroll
    for (int g = 0; g < 3; g++) {
        float2 p0 = up2(c2[g][0]), p1 = up2(c2[g][1]);
        gh[g][0] = p0.x; gh[g][1] = p0.y; gh[g][2] = p1.x; gh[g][3] = p1.y;
    }
    const float bhr = b_hh[j], bhz = b_hh[D_H + j], bhn = b_hh[2 * D_H + j];
#pragma unroll
    for (int u = 0; u < 4; u++) {
        int b = m0 + u;
        const float* gp = gi_s + (size_t)b * D3H;
        float gir = gp[j], giz = gp[D_H + j], gin = gp[2 * D_H + j];
        float hp  = h_prev[b * D_H + j];
        float r = 1.f / (1.f + expf(-(gir + gh[0][u] + bhr)));
        float z = 1.f / (1.f + expf(-(giz + gh[1][u] + bhz)));
        float n = tanhf(gin + r * (gh[2][u] + bhn));
        h_out[b * D_H + j] = (1.f - z) * n + z * hp;
    }
}

// ==============================================================================
// Kernel 3: logits = hs @ fc_w^T + fc_b, then log_softmax over 64 cols.
// 32 rows per CTA, 256 threads; warp-shuffle logsumexp.
// ==============================================================================
__global__ __launch_bounds__(256) void fc_lsm(
    const float* __restrict__ fc_w, const float* __restrict__ fc_b,
    float* __restrict__ out)
{
    __shared__ float2 Hs2[32][32];    // 8 KB (duplicated)
    __shared__ float  Ws [32][64];    // 8 KB
    __shared__ float  L  [32][64];    // 8 KB logits

    const int tid   = threadIdx.x;
    const int m_blk = blockIdx.x * 32;
    const int mg    = tid >> 4, ng = tid & 15;

    u64t c2[2][2] = {{0ull,0ull},{0ull,0ull}};

    for (int kt = 0; kt < D_H; kt += 32) {
        {
            int row = tid >> 3, kq = (tid & 7) * 4;
            float4 v = *(const float4*)(g_hs + (size_t)(m_blk + row) * D_H + kt + kq);
            Hs2[kq+0][row] = make_float2(v.x, v.x);
            Hs2[kq+1][row] = make_float2(v.y, v.y);
            Hs2[kq+2][row] = make_float2(v.z, v.z);
            Hs2[kq+3][row] = make_float2(v.w, v.w);
        }
#pragma unroll
        for (int t = 0; t < 2; t++) {
            int i = tid + t * 256;          // 0..511
            int row = i >> 3, kq = (i & 7) * 4;
            float4 v = *(const float4*)(fc_w + (size_t)row * D_H + kt + kq);
            Ws[kq+0][row] = v.x; Ws[kq+1][row] = v.y;
            Ws[kq+2][row] = v.z; Ws[kq+3][row] = v.w;
        }
        __syncthreads();
#pragma unroll
        for (int k = 0; k < 32; k++) {
            u64t a0  = *(const u64t*)&Hs2[k][mg*2];
            u64t a1  = *(const u64t*)&Hs2[k][mg*2 + 1];
            u64t b01 = *(const u64t*)&Ws[k][ng*4];
            u64t b23 = *(const u64t*)&Ws[k][ng*4 + 2];
            fma2(c2[0][0], a0, b01); fma2(c2[0][1], a0, b23);
            fma2(c2[1][0], a1, b01); fma2(c2[1][1], a1, b23);
        }
        __syncthreads();
    }

#pragma unroll
    for (int i = 0; i < 2; i++) {
        int row = mg*2 + i;
        float2 p0 = up2(c2[i][0]), p1 = up2(c2[i][1]);
        int n0 = ng * 4;
        L[row][n0+0] = p0.x + fc_b[n0+0];
        L[row][n0+1] = p0.y + fc_b[n0+1];
        L[row][n0+2] = p1.x + fc_b[n0+2];
        L[row][n0+3] = p1.y + fc_b[n0+3];
    }
    __syncthreads();

    const int w = tid >> 5, lane = tid & 31;
#pragma unroll
    for (int rr = 0; rr < 4; rr++) {
        int row = w * 4 + rr;
        float v0 = L[row][lane], v1 = L[row][lane + 32];
        float mx = fmaxf(v0, v1);
#pragma unroll
        for (int o = 16; o > 0; o >>= 1) mx = fmaxf(mx, __shfl_xor_sync(0xffffffffu, mx, o));
        float se = expf(v0 - mx) + expf(v1 - mx);
#pragma unroll
        for (int o = 16; o > 0; o >>= 1) se += __shfl_xor_sync(0xffffffffu, se, o);
        float lse = logf(se) + mx;
        int m = m_blk + row;
        int s = m >> 6, b = m & 63;                   // m = s*B + b
        float* op = out + ((size_t)b * SS + s) * D_OUT;
        op[lane]      = v0 - lse;
        op[lane + 32] = v1 - lse;
    }
}

// ==============================================================================
extern "C" void kernel_launch(void* const* d_in, const int* in_sizes, int n_in,
                              void* d_out, int out_size)
{
    (void)in_sizes; (void)n_in; (void)out_size;
    const int*   x    = (const int*)  d_in[0];
    const float* emb  = (const float*)d_in[1];
    const float* w_ih = (const float*)d_in[2];
    const float* w_hh = (const float*)d_in[3];
    const float* b_ih = (const float*)d_in[4];
    const float* b_hh = (const float*)d_in[5];
    const float* fc_w = (const float*)d_in[6];
    const float* fc_b = (const float*)d_in[7];
    float* out = (float*)d_out;

    gi_gemm<<<dim3(D3H / 128, (SS * BB) / 128), 256>>>(x, emb, w_ih, b_ih);
    for (int s = 0; s < SS; s++)
        gru_step<<<128, 128>>>(s, w_hh, b_hh);
    fc_lsm<<<(SS * BB) / 32, 256>>>(fc_w, fc_b, out);
}

// round 2
// speedup vs baseline: 1.9974x; 1.9974x over previous
#include <cuda_runtime.h>
#include <math.h>

#define VOCAB 32000
#define D_IN  512
#define D_H   1024
#define D3H   3072
#define D_OUT 64
#define BB    64
#define SS    256
#define NCTA  128

typedef unsigned long long u64t;

// ---------------- scratch (static device globals; zero-init at load) ----------
// gi transposed: [3H rows][S*B cols]  (row = gate*1024+j, col = s*64+b)
__device__ float g_gi[(size_t)D3H * SS * BB];
// h transposed: [s][j][b]
__device__ float g_hs[(size_t)SS * D_H * BB];
__device__ float g_h0[D_H * BB];                // all-zero h(-1), never written

// ---------------- grid barrier state ------------------------------------------
__device__ unsigned g_cnt = 0;
__device__ volatile unsigned g_flag = 0;        // cumulative barriers passed (monotonic)

// ---------------- f32x2 helpers ------------------------------------------------
__device__ __forceinline__ void fma2(u64t& c, u64t a, u64t b) {
    asm("fma.rn.f32x2 %0, %1, %2, %0;" : "+l"(c) : "l"(a), "l"(b));
}
__device__ __forceinline__ float2 up2(u64t v) {
    float2 r;
    asm("mov.b64 {%0, %1}, %2;" : "=f"(r.x), "=f"(r.y) : "l"(v));
    return r;
}
__device__ __forceinline__ u64t dup64(float w) {
    u64t r;
    asm("mov.b64 %0, {%1, %1};" : "=l"(r) : "f"(w));
    return r;
}

// ==============================================================================
// Kernel 1: g_gi[n][m] = sum_d w_ih[n][d] * emb[x(m)][d] + b_ih[n]
//           (transposed product: M'=3072 weight rows, N'=16384 token cols, K=512)
// 128x128x16 tile, 256 threads, 8x8 per thread, f32x2 inner loop.
// ==============================================================================
__global__ __launch_bounds__(256) void gi_gemm(
    const int* __restrict__ x, const float* __restrict__ emb,
    const float* __restrict__ w_ih, const float* __restrict__ b_ih)
{
    __shared__ float2 As2[16][128];   // 16 KB (w_ih side, duplicated)
    __shared__ float  Bs [16][128];   //  8 KB (gathered emb side)

    const int tid   = threadIdx.x;
    const int m_blk = blockIdx.y * 128;    // w_ih rows
    const int n_blk = blockIdx.x * 128;    // token cols

    const float* aptr[2]; int arow[2], akq[2];
    const float* bptr[2];
#pragma unroll
    for (int t = 0; t < 2; t++) {
        int i   = tid + t * 256;            // 0..511
        arow[t] = i >> 2;                   // 0..127
        akq[t]  = (i & 3) * 4;
        aptr[t] = w_ih + (size_t)(m_blk + arow[t]) * D_IN;
        int n = n_blk + arow[t];
        int s = n >> 6, b = n & 63;         // n = s*B + b
        int tok = x[b * SS + s];
        bptr[t] = emb + (size_t)tok * D_IN;
    }

    u64t c2[8][4];
#pragma unroll
    for (int i = 0; i < 8; i++)
#pragma unroll
        for (int j = 0; j < 4; j++) c2[i][j] = 0ull;

    const int ty = tid >> 4, tx = tid & 15;

    for (int kt = 0; kt < D_IN; kt += 16) {
#pragma unroll
        for (int t = 0; t < 2; t++) {
            float4 v = *(const float4*)(aptr[t] + kt + akq[t]);
            As2[akq[t]+0][arow[t]] = make_float2(v.x, v.x);
            As2[akq[t]+1][arow[t]] = make_float2(v.y, v.y);
            As2[akq[t]+2][arow[t]] = make_float2(v.z, v.z);
            As2[akq[t]+3][arow[t]] = make_float2(v.w, v.w);
            float4 w = *(const float4*)(bptr[t] + kt + akq[t]);
            Bs[akq[t]+0][arow[t]] = w.x;
            Bs[akq[t]+1][arow[t]] = w.y;
            Bs[akq[t]+2][arow[t]] = w.z;
            Bs[akq[t]+3][arow[t]] = w.w;
        }
        __syncthreads();
#pragma unroll
        for (int k = 0; k < 16; k++) {
            u64t ad[8], bb[4];
#pragma unroll
            for (int i = 0; i < 4; i++) {
                ad[i]     = *(const u64t*)&As2[k][ty*4 + i];
                ad[i + 4] = *(const u64t*)&As2[k][64 + ty*4 + i];
            }
            bb[0] = *(const u64t*)&Bs[k][tx*4];
            bb[1] = *(const u64t*)&Bs[k][tx*4 + 2];
            bb[2] = *(const u64t*)&Bs[k][64 + tx*4];
            bb[3] = *(const u64t*)&Bs[k][64 + tx*4 + 2];
#pragma unroll
            for (int i = 0; i < 8; i++)
#pragma unroll
                for (int j = 0; j < 4; j++)
                    fma2(c2[i][j], ad[i], bb[j]);
        }
        __syncthreads();
    }

#pragma unroll
    for (int i = 0; i < 8; i++) {
        int mi = (i < 4) ? (ty*4 + i) : (64 + ty*4 + (i - 4));
        size_t m = (size_t)(m_blk + mi);
        float bih = b_ih[m];
#pragma unroll
        for (int j = 0; j < 4; j++) {
            int nj = (j < 2) ? (tx*4 + j*2) : (64 + tx*4 + (j - 2)*2);
            int n  = n_blk + nj;
            float2 v = up2(c2[i][j]);
            v.x += bih;
            v.y += bih;
            *(float2*)(g_gi + m * (SS * BB) + n) = v;
        }
    }
}

// ==============================================================================
// Kernel 2: PERSISTENT GRU. 128 CTAs x 256 threads, all co-resident.
// CTA owns 8 j's (24 w_hh rows preloaded in smem). Per step:
//   stage h_prev[k][b] tiles (b-duplicated) -> f32x2 mainloop (splitK-4)
//   -> smem reduce -> fused gates -> transposed h store -> grid barrier.
// ==============================================================================
__global__ void __launch_bounds__(256, 1) gru_persistent(
    const float* __restrict__ w_hh, const float* __restrict__ b_hh)
{
    extern __shared__ float smem[];
    float* ws  = smem;                      // [1024][24]     96 KB
    float* hsd = smem + 24576;              // [128][128] dup 64 KB
    float* red = smem + 24576 + 16384;      // [4][3][8][64]  24 KB
    u64t* ws8  = (u64t*)ws;
    u64t* hsd8 = (u64t*)hsd;

    const int tid = threadIdx.x;
    const int j0  = blockIdx.x * 8;

    // ---- preload weight slice: ws[k][g*8+jj] = w_hh[g*1024 + j0+jj][k]
    for (int idx = tid; idx < 24 * 256; idx += 256) {
        int r = idx >> 8;            // 0..23
        int q = idx & 255;           // k quad
        int g = r >> 3, jj = r & 7;
        float4 v = *(const float4*)(w_hh + (size_t)(g * D_H + j0 + jj) * D_H + q * 4);
        ws[(q*4+0)*24 + r] = v.x;
        ws[(q*4+1)*24 + r] = v.y;
        ws[(q*4+2)*24 + r] = v.z;
        ws[(q*4+3)*24 + r] = v.w;
    }

    unsigned base = 0;
    if (tid == 0) base = g_flag;    // safe: flag can't advance until all CTAs arrive
    __syncthreads();

    const int g4 = tid >> 6;        // splitK group 0..3
    const int pos = tid & 63;
    const int bg  = pos >> 2;       // 0..15 (4 b's each)
    const int jp  = pos & 3;        // j-pair 0..3

    for (int s = 0; s < SS; s++) {
        const float* hp = (s == 0) ? g_h0 : (g_hs + (size_t)(s - 1) * D_H * BB);

        u64t acc[4][3];
#pragma unroll
        for (int u = 0; u < 4; u++)
#pragma unroll
            for (int g = 0; g < 3; g++) acc[u][g] = 0ull;

        // preload tile 0 into registers
        float4 rv[8];
#pragma unroll
        for (int i = 0; i < 8; i++) {
            int q = tid + i * 256;
            rv[i] = *(const float4*)(hp + (size_t)(q >> 4) * 64 + (q & 15) * 4);
        }

        for (int t = 0; t < 8; t++) {
            __syncthreads();
            // dup-store tile t: hsd[k][2b..2b+1] = h[k][b]
#pragma unroll
            for (int i = 0; i < 8; i++) {
                int q = tid + i * 256;
                int kl = q >> 4, bq = q & 15;
                float* dst = hsd + kl * 128 + bq * 8;
                ((float4*)dst)[0] = make_float4(rv[i].x, rv[i].x, rv[i].y, rv[i].y);
                ((float4*)dst)[1] = make_float4(rv[i].z, rv[i].z, rv[i].w, rv[i].w);
            }
            if (t < 7) {
#pragma unroll
                for (int i = 0; i < 8; i++) {
                    int q = tid + i * 256;
                    rv[i] = *(const float4*)(hp + (size_t)(t + 1) * 128 * 64
                                             + (size_t)(q >> 4) * 64 + (q & 15) * 4);
                }
            }
            __syncthreads();
            // compute this group's 32 k's of the tile
            const int kbase = t * 128 + g4 * 32;
#pragma unroll 4
            for (int kk = 0; kk < 32; kk++) {
                int kl = g4 * 32 + kk;
                u64t a0 = hsd8[kl*64 + bg*4 + 0];
                u64t a1 = hsd8[kl*64 + bg*4 + 1];
                u64t a2 = hsd8[kl*64 + bg*4 + 2];
                u64t a3 = hsd8[kl*64 + bg*4 + 3];
                int k = kbase + kk;
                u64t w0 = ws8[k*12 + 0*4 + jp];
                u64t w1 = ws8[k*12 + 1*4 + jp];
                u64t w2 = ws8[k*12 + 2*4 + jp];
                fma2(acc[0][0], a0, w0); fma2(acc[1][0], a1, w0);
                fma2(acc[2][0], a2, w0); fma2(acc[3][0], a3, w0);
                fma2(acc[0][1], a0, w1); fma2(acc[1][1], a1, w1);
                fma2(acc[2][1], a2, w1); fma2(acc[3][1], a3, w1);
                fma2(acc[0][2], a0, w2); fma2(acc[1][2], a1, w2);
                fma2(acc[2][2], a2, w2); fma2(acc[3][2], a3, w2);
            }
        }

        // splitK partial sums -> smem
        __syncthreads();
#pragma unroll
        for (int u = 0; u < 4; u++) {
            int b = bg * 4 + u;
#pragma unroll
            for (int g = 0; g < 3; g++) {
                float2 p = up2(acc[u][g]);
                red[((g4*3 + g)*8 + jp*2 + 0)*64 + b] = p.x;
                red[((g4*3 + g)*8 + jp*2 + 1)*64 + b] = p.y;
            }
        }
        __syncthreads();

        // gate epilogue: 512 outputs, 2 per thread, coalesced transposed store
        float* hout = g_hs + (size_t)s * D_H * BB;
        const float* gi0 = g_gi + (size_t)s * 64;
#pragma unroll
        for (int ii = 0; ii < 2; ii++) {
            int o  = tid + ii * 256;
            int jj = o >> 6, b = o & 63;
            int j  = j0 + jj;
            float ghr = 0.f, ghz = 0.f, ghn = 0.f;
#pragma unroll
            for (int g = 0; g < 4; g++) {
                ghr += red[((g*3 + 0)*8 + jj)*64 + b];
                ghz += red[((g*3 + 1)*8 + jj)*64 + b];
                ghn += red[((g*3 + 2)*8 + jj)*64 + b];
            }
            const float* gip = gi0 + (size_t)j * (SS * BB) + b;
            float gir = gip[0];
            float giz = gip[(size_t)D_H * SS * BB];
            float gin = gip[(size_t)2 * D_H * SS * BB];
            float hprev = hp[(size_t)j * 64 + b];
            float r = 1.f / (1.f + expf(-(gir + ghr + b_hh[j])));
            float z = 1.f / (1.f + expf(-(giz + ghz + b_hh[D_H + j])));
            float n = tanhf(gin + r * (ghn + b_hh[2 * D_H + j]));
            hout[(size_t)j * 64 + b] = (1.f - z) * n + z * hprev;
        }

        // ---- grid barrier ----
        __threadfence();
        __syncthreads();
        if (tid == 0) {
            unsigned target = base + (unsigned)(s + 1);
            unsigned old = atomicAdd(&g_cnt, 1u);
            if (old == NCTA - 1) {
                atomicExch(&g_cnt, 0u);
                __threadfence();
                atomicExch((unsigned*)&g_flag, target);
            } else {
                while (g_flag < target) __nanosleep(64);
            }
            __threadfence();
        }
        __syncthreads();
    }
}

// ==============================================================================
// Kernel 3: per-s CTA: logits[b][o] = sum_j hs[s][j][b]*fc_w[o][j] + fc_b,
// then log_softmax over o. Grid 256, 256 threads.
// ==============================================================================
__global__ __launch_bounds__(256) void fc_lsm(
    const float* __restrict__ fc_w, const float* __restrict__ fc_b,
    float* __restrict__ out)
{
    __shared__ float hst[32 * 64];     // [k][b] natural, 8 KB
    __shared__ float wst[64 * 36];     // [o][k] padded,  9 KB
    __shared__ float L  [64 * 65];     // logits, 16.25 KB

    const int tid = threadIdx.x;
    const int s   = blockIdx.x;
    const float* hs_s = g_hs + (size_t)s * D_H * BB;
    const int og = tid & 15, bg = tid >> 4;

    u64t acc[2][4];
#pragma unroll
    for (int u = 0; u < 2; u++)
#pragma unroll
        for (int v = 0; v < 4; v++) acc[u][v] = 0ull;
    u64t* hst8 = (u64t*)hst;

    for (int k0 = 0; k0 < D_H; k0 += 32) {
        __syncthreads();
#pragma unroll
        for (int i = 0; i < 2; i++) {
            int q = tid + i * 256;
            int kl = q >> 4, bq = q & 15;
            *(float4*)(hst + kl*64 + bq*4) =
                *(const float4*)(hs_s + (size_t)(k0 + kl) * 64 + bq * 4);
        }
#pragma unroll
        for (int i = 0; i < 2; i++) {
            int q = tid + i * 256;
            int o = q >> 3, kq = q & 7;
            *(float4*)(wst + o*36 + kq*4) =
                *(const float4*)(fc_w + (size_t)o * D_H + k0 + kq * 4);
        }
        __syncthreads();
#pragma unroll 4
        for (int kk = 0; kk < 32; kk++) {
            u64t h0 = hst8[kk*32 + bg*2 + 0];
            u64t h1 = hst8[kk*32 + bg*2 + 1];
#pragma unroll
            for (int v = 0; v < 4; v++) {
                u64t wd = dup64(wst[(og*4 + v)*36 + kk]);
                fma2(acc[0][v], h0, wd);
                fma2(acc[1][v], h1, wd);
            }
        }
    }

    __syncthreads();
#pragma unroll
    for (int u = 0; u < 2; u++) {
#pragma unroll
        for (int v = 0; v < 4; v++) {
            float2 p = up2(acc[u][v]);
            int o  = og * 4 + v;
            int b0 = bg * 4 + u * 2;
            float bias = fc_b[o];
            L[(b0 + 0)*65 + o] = p.x + bias;
            L[(b0 + 1)*65 + o] = p.y + bias;
        }
    }
    __syncthreads();

    const int w = tid >> 5, lane = tid & 31;
#pragma unroll
    for (int rr = 0; rr < 8; rr++) {
        int b = w * 8 + rr;
        float v0 = L[b*65 + lane], v1 = L[b*65 + 32 + lane];
        float mx = fmaxf(v0, v1);
#pragma unroll
        for (int o = 16; o > 0; o >>= 1) mx = fmaxf(mx, __shfl_xor_sync(0xffffffffu, mx, o));
        float se = expf(v0 - mx) + expf(v1 - mx);
#pragma unroll
        for (int o = 16; o > 0; o >>= 1) se += __shfl_xor_sync(0xffffffffu, se, o);
        float lse = logf(se) + mx;
        float* op = out + ((size_t)b * SS + s) * D_OUT;
        op[lane]      = v0 - lse;
        op[lane + 32] = v1 - lse;
    }
}

// ==============================================================================
extern "C" void kernel_launch(void* const* d_in, const int* in_sizes, int n_in,
                              void* d_out, int out_size)
{
    (void)in_sizes; (void)n_in; (void)out_size;
    const int*   x    = (const int*)  d_in[0];
    const float* emb  = (const float*)d_in[1];
    const float* w_ih = (const float*)d_in[2];
    const float* w_hh = (const float*)d_in[3];
    const float* b_ih = (const float*)d_in[4];
    const float* b_hh = (const float*)d_in[5];
    const float* fc_w = (const float*)d_in[6];
    const float* fc_b = (const float*)d_in[7];
    float* out = (float*)d_out;

    const int rec_smem = (24576 + 16384 + 6144) * 4;   // 184 KB
    cudaFuncSetAttribute(gru_persistent,
                         cudaFuncAttributeMaxDynamicSharedMemorySize, rec_smem);

    gi_gemm<<<dim3((SS * BB) / 128, D3H / 128), 256>>>(x, emb, w_ih, b_ih);
    gru_persistent<<<NCTA, 256, rec_smem>>>(w_hh, b_hh);
    fc_lsm<<<SS, 256>>>(fc_w, fc_b, out);
}

// round 3
// speedup vs baseline: 2.2975x; 1.1502x over previous
#include <cuda_runtime.h>
#include <math.h>

#define VOCAB 32000
#define D_IN  512
#define D_H   1024
#define D3H   3072
#define D_OUT 64
#define BB    64
#define SS    256
#define NCTA  128

typedef unsigned long long u64t;

// ---------------- scratch (static device globals; zero-init at load) ----------
// gi transposed: [3H rows][S*B cols]  (row = gate*1024+j, col = s*64+b)
__device__ float g_gi[(size_t)D3H * SS * BB];
// h transposed: [s][j][b]
__device__ float g_hs[(size_t)SS * D_H * BB];
__device__ float g_h0[D_H * BB];                // all-zero h(-1), never written

// ---------------- grid barrier state ------------------------------------------
__device__ unsigned g_cnt = 0;
__device__ volatile unsigned g_flag = 0;        // cumulative barriers passed (monotonic)

// ---------------- f32x2 helpers ------------------------------------------------
__device__ __forceinline__ void fma2(u64t& c, u64t a, u64t b) {
    asm("fma.rn.f32x2 %0, %1, %2, %0;" : "+l"(c) : "l"(a), "l"(b));
}
__device__ __forceinline__ float2 up2(u64t v) {
    float2 r;
    asm("mov.b64 {%0, %1}, %2;" : "=f"(r.x), "=f"(r.y) : "l"(v));
    return r;
}
__device__ __forceinline__ u64t dup64(float w) {
    u64t r;
    asm("mov.b64 %0, {%1, %1};" : "=l"(r) : "f"(w));
    return r;
}

// ==============================================================================
// Kernel 1: g_gi[n][m] = sum_d w_ih[n][d] * emb[x(m)][d] + b_ih[n]
//           (transposed product: M'=3072 weight rows, N'=16384 token cols, K=512)
// 128x128x16 tile, 256 threads, 8x8 per thread, f32x2 inner loop. (unchanged)
// ==============================================================================
__global__ __launch_bounds__(256) void gi_gemm(
    const int* __restrict__ x, const float* __restrict__ emb,
    const float* __restrict__ w_ih, const float* __restrict__ b_ih)
{
    __shared__ float2 As2[16][128];   // 16 KB (w_ih side, duplicated)
    __shared__ float  Bs [16][128];   //  8 KB (gathered emb side)

    const int tid   = threadIdx.x;
    const int m_blk = blockIdx.y * 128;    // w_ih rows
    const int n_blk = blockIdx.x * 128;    // token cols

    const float* aptr[2]; int arow[2], akq[2];
    const float* bptr[2];
#pragma unroll
    for (int t = 0; t < 2; t++) {
        int i   = tid + t * 256;            // 0..511
        arow[t] = i >> 2;                   // 0..127
        akq[t]  = (i & 3) * 4;
        aptr[t] = w_ih + (size_t)(m_blk + arow[t]) * D_IN;
        int n = n_blk + arow[t];
        int s = n >> 6, b = n & 63;         // n = s*B + b
        int tok = x[b * SS + s];
        bptr[t] = emb + (size_t)tok * D_IN;
    }

    u64t c2[8][4];
#pragma unroll
    for (int i = 0; i < 8; i++)
#pragma unroll
        for (int j = 0; j < 4; j++) c2[i][j] = 0ull;

    const int ty = tid >> 4, tx = tid & 15;

    for (int kt = 0; kt < D_IN; kt += 16) {
#pragma unroll
        for (int t = 0; t < 2; t++) {
            float4 v = *(const float4*)(aptr[t] + kt + akq[t]);
            As2[akq[t]+0][arow[t]] = make_float2(v.x, v.x);
            As2[akq[t]+1][arow[t]] = make_float2(v.y, v.y);
            As2[akq[t]+2][arow[t]] = make_float2(v.z, v.z);
            As2[akq[t]+3][arow[t]] = make_float2(v.w, v.w);
            float4 w = *(const float4*)(bptr[t] + kt + akq[t]);
            Bs[akq[t]+0][arow[t]] = w.x;
            Bs[akq[t]+1][arow[t]] = w.y;
            Bs[akq[t]+2][arow[t]] = w.z;
            Bs[akq[t]+3][arow[t]] = w.w;
        }
        __syncthreads();
#pragma unroll
        for (int k = 0; k < 16; k++) {
            u64t ad[8], bb[4];
#pragma unroll
            for (int i = 0; i < 4; i++) {
                ad[i]     = *(const u64t*)&As2[k][ty*4 + i];
                ad[i + 4] = *(const u64t*)&As2[k][64 + ty*4 + i];
            }
            bb[0] = *(const u64t*)&Bs[k][tx*4];
            bb[1] = *(const u64t*)&Bs[k][tx*4 + 2];
            bb[2] = *(const u64t*)&Bs[k][64 + tx*4];
            bb[3] = *(const u64t*)&Bs[k][64 + tx*4 + 2];
#pragma unroll
            for (int i = 0; i < 8; i++)
#pragma unroll
                for (int j = 0; j < 4; j++)
                    fma2(c2[i][j], ad[i], bb[j]);
        }
        __syncthreads();
    }

#pragma unroll
    for (int i = 0; i < 8; i++) {
        int mi = (i < 4) ? (ty*4 + i) : (64 + ty*4 + (i - 4));
        size_t m = (size_t)(m_blk + mi);
        float bih = b_ih[m];
#pragma unroll
        for (int j = 0; j < 4; j++) {
            int nj = (j < 2) ? (tx*4 + j*2) : (64 + tx*4 + (j - 2)*2);
            int n  = n_blk + nj;
            float2 v = up2(c2[i][j]);
            v.x += bih;
            v.y += bih;
            *(float2*)(g_gi + m * (SS * BB) + n) = v;
        }
    }
}

// ==============================================================================
// Kernel 2: PERSISTENT GRU. 128 CTAs x 256 threads, 1 CTA/SM.
// SMEM: ws [1024][24] 96KB  |  buf0/buf1 [128][128-dup] 64KB each (double buffer)
// red (24KB) aliases buf0 during the epilogue.
// Per step: prefetch gi/h_prev epilogue operands; 8 K-tiles, each:
//   LDG(t+1) -> compute(t) -> conflict-free dup STS(t+1) -> 1 sync.
// Then shuffle-free smem splitK reduce, fused gates, transposed h store,
// light grid barrier (fence in tid0 only, tight spin).
// ==============================================================================
__global__ void __launch_bounds__(256, 1) gru_persistent(
    const float* __restrict__ w_hh, const float* __restrict__ b_hh)
{
    extern __shared__ float smem[];
    float* ws   = smem;                       // [1024][24]        96 KB
    float* buf0 = smem + 24576;               // [128][128] dup    64 KB
    float* buf1 = smem + 24576 + 16384;       // [128][128] dup    64 KB
    float* red  = buf0;                       // [4][3][8][64]     24 KB (aliases buf0)
    u64t* ws8 = (u64t*)ws;

    const int tid  = threadIdx.x;
    const int j0   = blockIdx.x * 8;
    const int wid  = tid >> 5;
    const int lane = tid & 31;

    // ---- preload weight slice: ws[k][g*8+jj] = w_hh[g*1024 + j0+jj][k]
    for (int idx = tid; idx < 24 * 256; idx += 256) {
        int r = idx >> 8;            // 0..23
        int q = idx & 255;           // k quad
        int g = r >> 3, jj = r & 7;
        float4 v = *(const float4*)(w_hh + (size_t)(g * D_H + j0 + jj) * D_H + q * 4);
        ws[(q*4+0)*24 + r] = v.x;
        ws[(q*4+1)*24 + r] = v.y;
        ws[(q*4+2)*24 + r] = v.z;
        ws[(q*4+3)*24 + r] = v.w;
    }

    unsigned base = 0;
    if (tid == 0) base = g_flag;    // safe: flag can't advance until all CTAs arrive
    __syncthreads();

    const int g4  = tid >> 6;       // splitK group 0..3 (uniform per warp-pair)
    const int pos = tid & 63;
    const int bg  = pos >> 2;       // 0..15 (4 b's each)
    const int jp  = pos & 3;        // j-pair 0..3

    for (int s = 0; s < SS; s++) {
        const float* hp = (s == 0) ? g_h0 : (g_hs + (size_t)(s - 1) * D_H * BB);

        // ---- prefetch epilogue operands for this step (independent of h_prev
        //      except e_hp, which is also ready now) ----
        float e_gir[2], e_giz[2], e_gin[2], e_hp[2];
        const float* gi0 = g_gi + (size_t)s * 64;
#pragma unroll
        for (int ii = 0; ii < 2; ii++) {
            int o  = tid + ii * 256;
            int jj = o >> 6, b = o & 63;
            int j  = j0 + jj;
            const float* gip = gi0 + (size_t)j * (SS * BB) + b;
            e_gir[ii] = gip[0];
            e_giz[ii] = gip[(size_t)D_H * SS * BB];
            e_gin[ii] = gip[(size_t)2 * D_H * SS * BB];
            e_hp[ii]  = hp[(size_t)j * 64 + b];
        }

        u64t acc[4][3];
#pragma unroll
        for (int u = 0; u < 4; u++)
#pragma unroll
            for (int g = 0; g < 3; g++) acc[u][g] = 0ull;

        // ---- stage tile 0 directly: warp writes full contiguous dup rows ----
#pragma unroll
        for (int c = 0; c < 16; c++) {
            int row = wid * 16 + c;
            float2 v = *(const float2*)(hp + (size_t)row * 64 + lane * 2);
            *(float4*)(buf0 + row * 128 + lane * 4) = make_float4(v.x, v.x, v.y, v.y);
        }
        __syncthreads();

        for (int t = 0; t < 8; t++) {
            // prefetch next tile into registers (hidden behind compute)
            u64t pf[16];
            if (t < 7) {
#pragma unroll
                for (int c = 0; c < 16; c++) {
                    int row = wid * 16 + c;
                    pf[c] = *(const u64t*)(hp + (size_t)((t + 1) * 128 + row) * 64 + lane * 2);
                }
            }

            // compute tile t
            const u64t* b8 = (const u64t*)((t & 1) ? buf1 : buf0);
            const int kw = (t * 128 + g4 * 32) * 12;    // ws8 base for this group
#pragma unroll 4
            for (int kk = 0; kk < 32; kk++) {
                int kl = g4 * 32 + kk;
                ulonglong2 A01 = *(const ulonglong2*)(b8 + kl*64 + bg*4);
                ulonglong2 A23 = *(const ulonglong2*)(b8 + kl*64 + bg*4 + 2);
                u64t w0 = ws8[kw + kk*12 + 0*4 + jp];
                u64t w1 = ws8[kw + kk*12 + 1*4 + jp];
                u64t w2 = ws8[kw + kk*12 + 2*4 + jp];
                fma2(acc[0][0], A01.x, w0); fma2(acc[1][0], A01.y, w0);
                fma2(acc[2][0], A23.x, w0); fma2(acc[3][0], A23.y, w0);
                fma2(acc[0][1], A01.x, w1); fma2(acc[1][1], A01.y, w1);
                fma2(acc[2][1], A23.x, w1); fma2(acc[3][1], A23.y, w1);
                fma2(acc[0][2], A01.x, w2); fma2(acc[1][2], A01.y, w2);
                fma2(acc[2][2], A23.x, w2); fma2(acc[3][2], A23.y, w2);
            }

            if (t < 7) {
                float* dst = (t & 1) ? buf0 : buf1;     // the buffer NOT being read
#pragma unroll
                for (int c = 0; c < 16; c++) {
                    int row = wid * 16 + c;
                    float2 v = up2(pf[c]);
                    *(float4*)(dst + row * 128 + lane * 4) = make_float4(v.x, v.x, v.y, v.y);
                }
                __syncthreads();
            }
        }

        // ---- splitK partial sums -> red (aliases buf0; t=7 read buf1, disjoint)
#pragma unroll
        for (int u = 0; u < 4; u++) {
            int b = bg * 4 + u;
#pragma unroll
            for (int g = 0; g < 3; g++) {
                float2 p = up2(acc[u][g]);
                red[((g4*3 + g)*8 + jp*2 + 0)*64 + b] = p.x;
                red[((g4*3 + g)*8 + jp*2 + 1)*64 + b] = p.y;
            }
        }
        __syncthreads();

        // ---- gate epilogue: 512 outputs, 2 per thread, coalesced store ----
        float* hout = g_hs + (size_t)s * D_H * BB;
#pragma unroll
        for (int ii = 0; ii < 2; ii++) {
            int o  = tid + ii * 256;
            int jj = o >> 6, b = o & 63;
            int j  = j0 + jj;
            float ghr = 0.f, ghz = 0.f, ghn = 0.f;
#pragma unroll
            for (int g = 0; g < 4; g++) {
                ghr += red[((g*3 + 0)*8 + jj)*64 + b];
                ghz += red[((g*3 + 1)*8 + jj)*64 + b];
                ghn += red[((g*3 + 2)*8 + jj)*64 + b];
            }
            float r = 1.f / (1.f + expf(-(e_gir[ii] + ghr + b_hh[j])));
            float z = 1.f / (1.f + expf(-(e_giz[ii] + ghz + b_hh[D_H + j])));
            float n = tanhf(e_gin[ii] + r * (ghn + b_hh[2 * D_H + j]));
            hout[(size_t)j * 64 + b] = (1.f - z) * n + z * e_hp[ii];
        }

        // ---- grid barrier (fence only in tid0; syncthreads provides CTA HB) ----
        __syncthreads();
        if (tid == 0) {
            __threadfence();
            unsigned target = base + (unsigned)(s + 1);
            unsigned old = atomicAdd(&g_cnt, 1u);
            if (old == NCTA - 1) {
                atomicExch(&g_cnt, 0u);
                __threadfence();
                atomicExch((unsigned*)&g_flag, target);
            } else {
                while (g_flag < target) { }
            }
            __threadfence();
        }
        __syncthreads();
    }
}

// ==============================================================================
// Kernel 3: per-s CTA: logits[b][o] = sum_j hs[s][j][b]*fc_w[o][j] + fc_b,
// then log_softmax over o. Grid 256, 256 threads. (unchanged)
// ==============================================================================
__global__ __launch_bounds__(256) void fc_lsm(
    const float* __restrict__ fc_w, const float* __restrict__ fc_b,
    float* __restrict__ out)
{
    __shared__ float hst[32 * 64];     // [k][b] natural, 8 KB
    __shared__ float wst[64 * 36];     // [o][k] padded,  9 KB
    __shared__ float L  [64 * 65];     // logits, 16.25 KB

    const int tid = threadIdx.x;
    const int s   = blockIdx.x;
    const float* hs_s = g_hs + (size_t)s * D_H * BB;
    const int og = tid & 15, bg = tid >> 4;

    u64t acc[2][4];
#pragma unroll
    for (int u = 0; u < 2; u++)
#pragma unroll
        for (int v = 0; v < 4; v++) acc[u][v] = 0ull;
    u64t* hst8 = (u64t*)hst;

    for (int k0 = 0; k0 < D_H; k0 += 32) {
        __syncthreads();
#pragma unroll
        for (int i = 0; i < 2; i++) {
            int q = tid + i * 256;
            int kl = q >> 4, bq = q & 15;
            *(float4*)(hst + kl*64 + bq*4) =
                *(const float4*)(hs_s + (size_t)(k0 + kl) * 64 + bq * 4);
        }
#pragma unroll
        for (int i = 0; i < 2; i++) {
            int q = tid + i * 256;
            int o = q >> 3, kq = q & 7;
            *(float4*)(wst + o*36 + kq*4) =
                *(const float4*)(fc_w + (size_t)o * D_H + k0 + kq * 4);
        }
        __syncthreads();
#pragma unroll 4
        for (int kk = 0; kk < 32; kk++) {
            u64t h0 = hst8[kk*32 + bg*2 + 0];
            u64t h1 = hst8[kk*32 + bg*2 + 1];
#pragma unroll
            for (int v = 0; v < 4; v++) {
                u64t wd = dup64(wst[(og*4 + v)*36 + kk]);
                fma2(acc[0][v], h0, wd);
                fma2(acc[1][v], h1, wd);
            }
        }
    }

    __syncthreads();
#pragma unroll
    for (int u = 0; u < 2; u++) {
#pragma unroll
        for (int v = 0; v < 4; v++) {
            float2 p = up2(acc[u][v]);
            int o  = og * 4 + v;
            int b0 = bg * 4 + u * 2;
            float bias = fc_b[o];
            L[(b0 + 0)*65 + o] = p.x + bias;
            L[(b0 + 1)*65 + o] = p.y + bias;
        }
    }
    __syncthreads();

    const int w = tid >> 5, lane = tid & 31;
#pragma unroll
    for (int rr = 0; rr < 8; rr++) {
        int b = w * 8 + rr;
        float v0 = L[b*65 + lane], v1 = L[b*65 + 32 + lane];
        float mx = fmaxf(v0, v1);
#pragma unroll
        for (int o = 16; o > 0; o >>= 1) mx = fmaxf(mx, __shfl_xor_sync(0xffffffffu, mx, o));
        float se = expf(v0 - mx) + expf(v1 - mx);
#pragma unroll
        for (int o = 16; o > 0; o >>= 1) se += __shfl_xor_sync(0xffffffffu, se, o);
        float lse = logf(se) + mx;
        float* op = out + ((size_t)b * SS + s) * D_OUT;
        op[lane]      = v0 - lse;
        op[lane + 32] = v1 - lse;
    }
}

// ==============================================================================
extern "C" void kernel_launch(void* const* d_in, const int* in_sizes, int n_in,
                              void* d_out, int out_size)
{
    (void)in_sizes; (void)n_in; (void)out_size;
    const int*   x    = (const int*)  d_in[0];
    const float* emb  = (const float*)d_in[1];
    const float* w_ih = (const float*)d_in[2];
    const float* w_hh = (const float*)d_in[3];
    const float* b_ih = (const float*)d_in[4];
    const float* b_hh = (const float*)d_in[5];
    const float* fc_w = (const float*)d_in[6];
    const float* fc_b = (const float*)d_in[7];
    float* out = (float*)d_out;

    const int rec_smem = (24576 + 16384 + 16384) * 4;   // 224 KB
    cudaFuncSetAttribute(gru_persistent,
                         cudaFuncAttributeMaxDynamicSharedMemorySize, rec_smem);

    gi_gemm<<<dim3((SS * BB) / 128, D3H / 128), 256>>>(x, emb, w_ih, b_ih);
    gru_persistent<<<NCTA, 256, rec_smem>>>(w_hh, b_hh);
    fc_lsm<<<SS, 256>>>(fc_w, fc_b, out);
}